// round 17
// baseline (speedup 1.0000x reference)
#include <cuda_runtime.h>
#include <cuda_fp16.h>
#include <math.h>
#include <stdint.h>

#define MAX_EDGES 320000
#define MAX_NODES 32768

// Weight fragments, B-operand layout for mma.m16n8k16 (col-major B), fp16.
#define FRAG_L1 0
#define FRAG_L2 256
#define FRAG_L3 1280
#define FRAG_L4 2304
#define FRAG_TOTAL 6400
__device__ uint2 g_wfrag[FRAG_TOTAL];

// Counting-sort scratch
__device__ int g_cnt[MAX_NODES];
__device__ int g_cur[MAX_NODES];
__device__ int g_bsum[MAX_NODES / 256 + 1];
__device__ int g_eidx[MAX_EDGES];

#define M2 132   /* floats per staged row: two 64-wide chunks + 4 pad */

// ---------------------------------------------------------------------------
__device__ __forceinline__ void mma16816(float* c,
                                         uint32_t a0, uint32_t a1, uint32_t a2, uint32_t a3,
                                         uint32_t b0, uint32_t b1) {
    asm volatile(
        "mma.sync.aligned.m16n8k16.row.col.f32.f16.f16.f32 "
        "{%0,%1,%2,%3}, {%4,%5,%6,%7}, {%8,%9}, {%0,%1,%2,%3};"
        : "+f"(c[0]), "+f"(c[1]), "+f"(c[2]), "+f"(c[3])
        : "r"(a0), "r"(a1), "r"(a2), "r"(a3), "r"(b0), "r"(b1));
}

__device__ __forceinline__ void red4(float* p, float a, float b, float c, float d) {
    asm volatile("red.global.add.v4.f32 [%0], {%1,%2,%3,%4};"
                 :: "l"(p), "f"(a), "f"(b), "f"(c), "f"(d) : "memory");
}

__device__ __forceinline__ void split2(float v0, float v1, uint32_t& hi, uint32_t& lo) {
    __half h0 = __float2half_rn(v0);
    __half h1 = __float2half_rn(v1);
    float r0 = v0 - __half2float(h0);
    float r1 = v1 - __half2float(h1);
    __half l0 = __float2half_rn(r0);
    __half l1 = __float2half_rn(r1);
    hi = (uint32_t)__half_as_ushort(h0) | ((uint32_t)__half_as_ushort(h1) << 16);
    lo = (uint32_t)__half_as_ushort(l0) | ((uint32_t)__half_as_ushort(l1) << 16);
}

__device__ __forceinline__ float silu_act(float x, float act) {
    return __fdividef(x, 1.0f + __expf(-x)) * act;
}

// ---------------------------------------------------------------------------
// Counting sort by receiver: zero -> hist -> 2-level scan -> scatter
// ---------------------------------------------------------------------------
__global__ void zero_kernel(int n) {
    int i = blockIdx.x * blockDim.x + threadIdx.x;
    if (i < n) g_cnt[i] = 0;
}

__global__ void hist_kernel(const int* __restrict__ receivers, int n_edges) {
    int e = blockIdx.x * blockDim.x + threadIdx.x;
    if (e < n_edges) atomicAdd(&g_cnt[receivers[e]], 1);
}

// Level 1: per-256-node-bucket exclusive prefix into g_cur; bucket total -> g_bsum.
__global__ void scan1_kernel(int n) {
    __shared__ int sh[256];
    int tid = threadIdx.x;
    int i = blockIdx.x * 256 + tid;
    int c = (i < n) ? g_cnt[i] : 0;
    sh[tid] = c;
    __syncthreads();
    int acc = c;
    for (int d = 1; d < 256; d <<= 1) {
        int v = (tid >= d) ? sh[tid - d] : 0;
        __syncthreads();
        acc += v;
        sh[tid] = acc;
        __syncthreads();
    }
    if (i < n) g_cur[i] = acc - c;              // exclusive within bucket
    if (tid == 255) g_bsum[blockIdx.x] = acc;   // bucket total
}

// Level 2: exclusive scan of bucket totals (<=128 buckets, one tiny block).
__global__ void scan2_kernel(int nb) {
    __shared__ int sh[256];
    int tid = threadIdx.x;
    int c = (tid < nb) ? g_bsum[tid] : 0;
    sh[tid] = c;
    __syncthreads();
    int acc = c;
    for (int d = 1; d < 256; d <<= 1) {
        int v = (tid >= d) ? sh[tid - d] : 0;
        __syncthreads();
        acc += v;
        sh[tid] = acc;
        __syncthreads();
    }
    if (tid < nb) g_bsum[tid] = acc - c;        // exclusive bucket base
}

__global__ void scatter_sort_kernel(const int* __restrict__ receivers, int n_edges) {
    int e = blockIdx.x * blockDim.x + threadIdx.x;
    if (e < n_edges) {
        int r = receivers[e];
        int pos = g_bsum[r >> 8] + atomicAdd(&g_cur[r], 1);
        g_eidx[pos] = e;
    }
}

// ---------------------------------------------------------------------------
// Setup: fp32 weights -> fragment-ordered fp16 (scales folded).
// L4: columns PERMUTED; 1/sqrt(16) folded in.
// ---------------------------------------------------------------------------
__global__ void build_frags(const float* __restrict__ w0, const float* __restrict__ w1,
                            const float* __restrict__ w2, const float* __restrict__ w3)
{
    int idx = blockIdx.x * blockDim.x + threadIdx.x;
    if (idx >= FRAG_TOTAL) return;

    const float* src; int K, N, ktiles, base; float scale;
    if (idx < FRAG_L2)      { base = FRAG_L1; src = w0; K = 8;  N = 64;  ktiles = 1; scale = 0.35355339059327373f; }
    else if (idx < FRAG_L3) { base = FRAG_L2; src = w1; K = 64; N = 64;  ktiles = 4; scale = 0.125f; }
    else if (idx < FRAG_L4) { base = FRAG_L3; src = w2; K = 64; N = 64;  ktiles = 4; scale = 0.125f; }
    else                    { base = FRAG_L4; src = w3; K = 64; N = 256; ktiles = 4; scale = 0.125f * 0.25f; }

    int fid  = idx - base;
    int lane = fid & 31, pair = fid >> 5;
    int kt = pair % ktiles, nt = pair / ktiles;
    int g = lane >> 2, t = lane & 3;

    int n;
    if (base == FRAG_L4) {
        int chunk = nt >> 3, nt_in = nt & 7;
        n = chunk * 64 + ((g >> 1) << 4) + nt_in * 2 + (g & 1);
    } else {
        n = nt * 8 + g;
    }

    int kb = kt * 16 + 2 * t;
    int ks[4] = { kb, kb + 1, kb + 8, kb + 9 };

    uint16_t h[4];
#pragma unroll
    for (int i = 0; i < 4; i++) {
        float v = (ks[i] < K) ? src[ks[i] * N + n] * scale : 0.0f;
        h[i] = __half_as_ushort(__float2half_rn(v));
    }
    uint2 o;
    o.x = (uint32_t)h[0] | ((uint32_t)h[1] << 16);
    o.y = (uint32_t)h[2] | ((uint32_t)h[3] << 16);
    g_wfrag[idx] = o;
}

// ---------------------------------------------------------------------------
__device__ __forceinline__ void act_split(const float* acc, uint32_t* ah, uint32_t* al,
                                          float act) {
#pragma unroll
    for (int kt = 0; kt < 4; kt++) {
        const float* T0 = acc + (2 * kt) * 4;
        const float* T1 = acc + (2 * kt + 1) * 4;
        split2(silu_act(T0[0], act), silu_act(T0[1], act), ah[kt * 4 + 0], al[kt * 4 + 0]);
        split2(silu_act(T0[2], act), silu_act(T0[3], act), ah[kt * 4 + 1], al[kt * 4 + 1]);
        split2(silu_act(T1[0], act), silu_act(T1[1], act), ah[kt * 4 + 2], al[kt * 4 + 2]);
        split2(silu_act(T1[2], act), silu_act(T1[3], act), ah[kt * 4 + 3], al[kt * 4 + 3]);
    }
}

template <int CHUNK>
__device__ __forceinline__ void mma_chunk(const uint32_t* ah, const uint32_t* al,
                                          int lane, float* acc)
{
#pragma unroll
    for (int i = 0; i < 32; i++) acc[i] = 0.f;
#pragma unroll
    for (int nt = 0; nt < 8; nt++) {
#pragma unroll
        for (int kt = 0; kt < 4; kt++) {
            uint2 f = __ldg(&g_wfrag[FRAG_L4 + ((CHUNK * 8 + nt) * 4 + kt) * 32 + lane]);
            float* c = &acc[nt * 4];
            const uint32_t* A = &ah[kt * 4];
            const uint32_t* L = &al[kt * 4];
            mma16816(c, A[0], A[1], A[2], A[3], f.x, f.y);
            mma16816(c, L[0], L[1], L[2], L[3], f.x, f.y);
        }
    }
}

__device__ __forceinline__ void stage(const float* acc, float* wmsg, int off,
                                      int g, int t)
{
#pragma unroll
    for (int q = 0; q < 4; q++) {
        *(float4*)&wmsg[g * M2 + off + t * 16 + 4 * q] =
            make_float4(acc[8 * q + 0], acc[8 * q + 1], acc[8 * q + 4], acc[8 * q + 5]);
        *(float4*)&wmsg[(g + 8) * M2 + off + t * 16 + 4 * q] =
            make_float4(acc[8 * q + 2], acc[8 * q + 3], acc[8 * q + 6], acc[8 * q + 7]);
    }
}

// ---------------------------------------------------------------------------
// Fused kernel: MLP + paired-chunk scatter with receiver-run merging.
// ---------------------------------------------------------------------------
__global__ void __launch_bounds__(128, 5)
fused_kernel(const float* __restrict__ edge_attrs,
             const float* __restrict__ node_feats,
             const int* __restrict__ senders,
             const int* __restrict__ receivers,
             float* __restrict__ out,
             int n_edges, float act)
{
    __shared__ float smsg[4][16 * M2];
    __shared__ int   sh_e[64];
    __shared__ int   sh_s[64];
    __shared__ int   sh_r[64];
    __shared__ float sh_ev[64 * 3];

    int tid = threadIdx.x, lane = tid & 31, warp = tid >> 5;
    int g = lane >> 2, t = lane & 3;
    int wbase = blockIdx.x * 64 + warp * 16;
    if (wbase >= n_edges) return;

    if (lane < 16) {
        int pos = wbase + lane;
        int el = warp * 16 + lane;
        if (pos < n_edges) {
            int e = __ldg(&g_eidx[pos]);
            sh_e[el] = e;
            sh_s[el] = __ldg(senders + e);
            sh_r[el] = __ldg(receivers + e);
            const float* ea = edge_attrs + (size_t)e * 11;
            sh_ev[el * 3 + 0] = __ldg(ea + 8);
            sh_ev[el * 3 + 1] = __ldg(ea + 9);
            sh_ev[el * 3 + 2] = __ldg(ea + 10);
        } else {
            sh_e[el] = 0; sh_s[el] = 0; sh_r[el] = -1;
            sh_ev[el * 3 + 0] = 0.f; sh_ev[el * 3 + 1] = 0.f; sh_ev[el * 3 + 2] = 0.f;
        }
    }
    __syncwarp();

    // ---- Layer 1 A fragments (K=8, cols 8..15 zero), via sorted edge ids ----
    bool valid0 = (wbase + g)     < n_edges;
    bool valid1 = (wbase + g + 8) < n_edges;
    float x00 = 0.f, x01 = 0.f, x10 = 0.f, x11 = 0.f;
    if (valid0) {
        const float* p = edge_attrs + (size_t)sh_e[warp * 16 + g] * 11 + 2 * t;
        x00 = __ldg(p); x01 = __ldg(p + 1);
    }
    if (valid1) {
        const float* p = edge_attrs + (size_t)sh_e[warp * 16 + g + 8] * 11 + 2 * t;
        x10 = __ldg(p); x11 = __ldg(p + 1);
    }
    uint32_t a0h, a0l, a1h, a1l;
    split2(x00, x01, a0h, a0l);
    split2(x10, x11, a1h, a1l);

    float acc[32];
    uint32_t ah[16], al[16];

    // ---- Layer 1 ----
#pragma unroll
    for (int i = 0; i < 32; i++) acc[i] = 0.f;
#pragma unroll
    for (int nt = 0; nt < 8; nt++) {
        uint2 f = __ldg(&g_wfrag[FRAG_L1 + nt * 32 + lane]);
        float* c = &acc[nt * 4];
        mma16816(c, a0h, a1h, 0u, 0u, f.x, f.y);
        mma16816(c, a0l, a1l, 0u, 0u, f.x, f.y);
    }
    act_split(acc, ah, al, act);

    // ---- Layer 2 ----
#pragma unroll
    for (int i = 0; i < 32; i++) acc[i] = 0.f;
#pragma unroll
    for (int nt = 0; nt < 8; nt++) {
#pragma unroll
        for (int kt = 0; kt < 4; kt++) {
            uint2 f = __ldg(&g_wfrag[FRAG_L2 + (nt * 4 + kt) * 32 + lane]);
            float* c = &acc[nt * 4];
            const uint32_t* A = &ah[kt * 4];
            const uint32_t* L = &al[kt * 4];
            mma16816(c, A[0], A[1], A[2], A[3], f.x, f.y);
            mma16816(c, L[0], L[1], L[2], L[3], f.x, f.y);
        }
    }
    act_split(acc, ah, al, act);

    // ---- Layer 3 ----
#pragma unroll
    for (int i = 0; i < 32; i++) acc[i] = 0.f;
#pragma unroll
    for (int nt = 0; nt < 8; nt++) {
#pragma unroll
        for (int kt = 0; kt < 4; kt++) {
            uint2 f = __ldg(&g_wfrag[FRAG_L3 + (nt * 4 + kt) * 32 + lane]);
            float* c = &acc[nt * 4];
            const uint32_t* A = &ah[kt * 4];
            const uint32_t* L = &al[kt * 4];
            mma16816(c, A[0], A[1], A[2], A[3], f.x, f.y);
            mma16816(c, L[0], L[1], L[2], L[3], f.x, f.y);
        }
    }
    act_split(acc, ah, al, act);

    // ---- Layer 4, paired by gather operand, run-merged atomics ----
    float* wmsg = smsg[warp];
    const int*   ws  = sh_s  + warp * 16;
    const int*   wr  = sh_r  + warp * 16;
    const float* wev = sh_ev + warp * 48;
    int edges_left = n_edges - wbase;
    const float IS3 = 0.57735026918962576f;
    int half = lane >> 4;
    int l = lane & 15;
    int elbase = half * 8;

    // === Pair A: chunks 0 and 3 (both gather ms = nrow[0:64]) ===
    mma_chunk<0>(ah, al, lane, acc);
    stage(acc, wmsg, 0, g, t);
    mma_chunk<3>(ah, al, lane, acc);
    stage(acc, wmsg, 64, g, t);
    __syncwarp();

    {
        float4 aA = make_float4(0.f, 0.f, 0.f, 0.f);
        float4 aB0 = aA, aB1 = aA, aB2 = aA;
        int prevr = -1;
        float* orow = out;
#pragma unroll 1
        for (int p = 0; p < 8; p++) {
            int el = elbase + p;
            if (el >= edges_left) break;
            int r = wr[el];
            if (r != prevr) {
                if (prevr >= 0) {
                    red4(orow + 4 * l, aA.x, aA.y, aA.z, aA.w);
                    float* po = orow + 320 + 12 * l;
                    red4(po,     aB0.x, aB0.y, aB0.z, aB0.w);
                    red4(po + 4, aB1.x, aB1.y, aB1.z, aB1.w);
                    red4(po + 8, aB2.x, aB2.y, aB2.z, aB2.w);
                }
                prevr = r;
                orow = out + (size_t)r * 512;
                aA = make_float4(0.f, 0.f, 0.f, 0.f);
                aB0 = aA; aB1 = aA; aB2 = aA;
            }
            int s = ws[el];
            float ev0 = wev[el * 3], ev1 = wev[el * 3 + 1], ev2 = wev[el * 3 + 2];
            const float* nrow = node_feats + (size_t)s * 256;
            float4 mx0 = *(const float4*)&wmsg[el * M2 + 4 * l];
            float4 mx3 = *(const float4*)&wmsg[el * M2 + 64 + 4 * l];
            float4 ms = __ldg((const float4*)(nrow + 4 * l));
            aA.x += ms.x * mx0.x; aA.y += ms.y * mx0.y;
            aA.z += ms.z * mx0.z; aA.w += ms.w * mx0.w;
            float d0 = ms.x * mx3.x, d1 = ms.y * mx3.y;
            float d2 = ms.z * mx3.z, d3 = ms.w * mx3.w;
            aB0.x += d0 * ev0; aB0.y += d0 * ev1; aB0.z += d0 * ev2; aB0.w += d1 * ev0;
            aB1.x += d1 * ev1; aB1.y += d1 * ev2; aB1.z += d2 * ev0; aB1.w += d2 * ev1;
            aB2.x += d2 * ev2; aB2.y += d3 * ev0; aB2.z += d3 * ev1; aB2.w += d3 * ev2;
        }
        if (prevr >= 0) {
            red4(orow + 4 * l, aA.x, aA.y, aA.z, aA.w);
            float* po = orow + 320 + 12 * l;
            red4(po,     aB0.x, aB0.y, aB0.z, aB0.w);
            red4(po + 4, aB1.x, aB1.y, aB1.z, aB1.w);
            red4(po + 8, aB2.x, aB2.y, aB2.z, aB2.w);
        }
    }
    __syncwarp();

    // === Pair B: chunks 1 and 2 (both gather v = nrow[64:256]) ===
    mma_chunk<1>(ah, al, lane, acc);
    stage(acc, wmsg, 0, g, t);
    mma_chunk<2>(ah, al, lane, acc);
    stage(acc, wmsg, 64, g, t);
    __syncwarp();

    {
        float4 aS = make_float4(0.f, 0.f, 0.f, 0.f);
        float4 aV0 = aS, aV1 = aS, aV2 = aS;
        int prevr = -1;
        float* orow = out;
#pragma unroll 1
        for (int p = 0; p < 8; p++) {
            int el = elbase + p;
            if (el >= edges_left) break;
            int r = wr[el];
            if (r != prevr) {
                if (prevr >= 0) {
                    red4(orow + 64 + 4 * l, aS.x, aS.y, aS.z, aS.w);
                    float* po = orow + 128 + 12 * l;
                    red4(po,     aV0.x, aV0.y, aV0.z, aV0.w);
                    red4(po + 4, aV1.x, aV1.y, aV1.z, aV1.w);
                    red4(po + 8, aV2.x, aV2.y, aV2.z, aV2.w);
                }
                prevr = r;
                orow = out + (size_t)r * 512;
                aS = make_float4(0.f, 0.f, 0.f, 0.f);
                aV0 = aS; aV1 = aS; aV2 = aS;
            }
            int s = ws[el];
            float ev0 = wev[el * 3], ev1 = wev[el * 3 + 1], ev2 = wev[el * 3 + 2];
            const float* nrow = node_feats + (size_t)s * 256;
            float4 mx1 = *(const float4*)&wmsg[el * M2 + 4 * l];
            float4 mx2 = *(const float4*)&wmsg[el * M2 + 64 + 4 * l];
            const float4* vp = (const float4*)(nrow + 64 + 12 * l);
            float4 va = __ldg(vp), vb = __ldg(vp + 1), vc = __ldg(vp + 2);
            float t0 = (va.x * ev0 + va.y * ev1 + va.z * ev2) * IS3;
            float t1 = (va.w * ev0 + vb.x * ev1 + vb.y * ev2) * IS3;
            float t2 = (vb.z * ev0 + vb.w * ev1 + vc.x * ev2) * IS3;
            float t3 = (vc.y * ev0 + vc.z * ev1 + vc.w * ev2) * IS3;
            aS.x += t0 * mx1.x; aS.y += t1 * mx1.y; aS.z += t2 * mx1.z; aS.w += t3 * mx1.w;
            aV0.x += va.x * mx2.x; aV0.y += va.y * mx2.x; aV0.z += va.z * mx2.x; aV0.w += va.w * mx2.y;
            aV1.x += vb.x * mx2.y; aV1.y += vb.y * mx2.y; aV1.z += vb.z * mx2.z; aV1.w += vb.w * mx2.z;
            aV2.x += vc.x * mx2.z; aV2.y += vc.y * mx2.w; aV2.z += vc.z * mx2.w; aV2.w += vc.w * mx2.w;
        }
        if (prevr >= 0) {
            red4(orow + 64 + 4 * l, aS.x, aS.y, aS.z, aS.w);
            float* po = orow + 128 + 12 * l;
            red4(po,     aV0.x, aV0.y, aV0.z, aV0.w);
            red4(po + 4, aV1.x, aV1.y, aV1.z, aV1.w);
            red4(po + 8, aV2.x, aV2.y, aV2.z, aV2.w);
        }
    }
}

// ---------------------------------------------------------------------------
// Host
// ---------------------------------------------------------------------------
static float compute_act_cst() {
    const int    N = 20000;
    const double a = -14.0, b = 14.0;
    const double h = (b - a) / N;
    double sum = 0.0;
    for (int i = 0; i <= N; i++) {
        double xx  = a + h * i;
        double sig = 1.0 / (1.0 + exp(-xx));
        double sl  = xx * sig;
        double f   = exp(-0.5 * xx * xx) * sl * sl;
        double wq  = (i == 0 || i == N) ? 1.0 : ((i & 1) ? 4.0 : 2.0);
        sum += wq * f;
    }
    sum *= h / 3.0;
    sum /= sqrt(2.0 * M_PI);
    return (float)(1.0 / sqrt(sum));
}

extern "C" void kernel_launch(void* const* d_in, const int* in_sizes, int n_in,
                              void* d_out, int out_size)
{
    const float* node_feats = (const float*)d_in[0];
    const float* edge_attrs = (const float*)d_in[1];
    const int*   senders    = (const int*)d_in[2];
    const int*   receivers  = (const int*)d_in[3];
    const float* w0         = (const float*)d_in[4];
    const float* w1         = (const float*)d_in[5];
    const float* w2         = (const float*)d_in[6];
    const float* w3         = (const float*)d_in[7];
    float*       out        = (float*)d_out;

    int n_edges = in_sizes[2];
    if (n_edges > MAX_EDGES) n_edges = MAX_EDGES;
    int n_nodes = out_size / 512;
    if (n_nodes > MAX_NODES) n_nodes = MAX_NODES;
    int n_buckets = (n_nodes + 255) / 256;

    float act = compute_act_cst();

    cudaMemsetAsync(d_out, 0, (size_t)out_size * sizeof(float));

    build_frags<<<(FRAG_TOTAL + 255) / 256, 256>>>(w0, w1, w2, w3);

    // Counting sort of edges by receiver -> g_eidx (2-level parallel scan)
    zero_kernel<<<(n_nodes + 255) / 256, 256>>>(n_nodes);
    hist_kernel<<<(n_edges + 255) / 256, 256>>>(receivers, n_edges);
    scan1_kernel<<<n_buckets, 256>>>(n_nodes);
    scan2_kernel<<<1, 256>>>(n_buckets);
    scatter_sort_kernel<<<(n_edges + 255) / 256, 256>>>(receivers, n_edges);

    int blocks = (n_edges + 63) / 64;
    fused_kernel<<<blocks, 128>>>(edge_attrs, node_feats, senders,
                                  receivers, out, n_edges, act);
}